// round 4
// baseline (speedup 1.0000x reference)
#include <cuda_runtime.h>
#include <cuda_fp16.h>

#define NN 50000
#define NE 1600000
#define NEG 0.2f

// ---------------- scratch (device globals; no allocation allowed) ----------
__device__ float4  g_hq[NN];           // per-node h_q (4 heads)
__device__ float4  g_kact[NN];         // per-node leaky(x@Wk^T)
__device__ float4  g_qagg[NN];         // per-node aggregated q
__device__ __half  g_hproj[NN * 128];  // per-node x@Wl^T + bl, fp16
__device__ float4  g_sc[NE];           // per-edge scores, then exp(scores-max)
__device__ int     g_deg[NN];
__device__ int     g_rowptr[NN + 1];
__device__ int     g_pos[NN];
__device__ int     g_ccol[NE];         // CSR: col indices sorted by row

// ---------------- CSR build ----------------
__global__ void kzero() {
    int i = blockIdx.x * blockDim.x + threadIdx.x;
    if (i < NN) g_deg[i] = 0;
}

__global__ void khist(const int* __restrict__ ei) {
    int e = blockIdx.x * blockDim.x + threadIdx.x;
    if (e < NE) atomicAdd(&g_deg[ei[e]], 1);
}

__global__ void kscan() {
    __shared__ int sums[1024];
    const int T = 1024;
    const int ITEMS = (NN + T - 1) / T;  // 49
    int t = threadIdx.x;
    int start = t * ITEMS;
    int end = min(start + ITEMS, NN);
    int s = 0;
    for (int i = start; i < end; i++) s += g_deg[i];
    sums[t] = s;
    __syncthreads();
    for (int off = 1; off < T; off <<= 1) {
        int v = (t >= off) ? sums[t - off] : 0;
        __syncthreads();
        sums[t] += v;
        __syncthreads();
    }
    int prefix = (t == 0) ? 0 : sums[t - 1];
    for (int i = start; i < end; i++) {
        g_rowptr[i] = prefix;
        g_pos[i] = prefix;
        prefix += g_deg[i];
    }
    if (t == T - 1) g_rowptr[NN] = prefix;
}

__global__ void kscatter(const int* __restrict__ ei) {
    int e = blockIdx.x * blockDim.x + threadIdx.x;
    if (e < NE) {
        int r = ei[e];
        int p = atomicAdd(&g_pos[r], 1);
        g_ccol[p] = ei[NE + e];
    }
}

// ---------------- per-node small projections: h_q, k_act -------------------
__global__ void kprojsmall(const float* __restrict__ x,
                           const float* __restrict__ Wq,
                           const float* __restrict__ Wk) {
    int w = (blockIdx.x * blockDim.x + threadIdx.x) >> 5;
    int lane = threadIdx.x & 31;
    if (w >= NN) return;
    float4 xv = ((const float4*)x)[w * 32 + lane];
    float a[8];
#pragma unroll
    for (int h = 0; h < 4; h++) {
        float4 q = ((const float4*)Wq)[h * 32 + lane];
        float4 k = ((const float4*)Wk)[h * 32 + lane];
        a[h]     = xv.x * q.x + xv.y * q.y + xv.z * q.z + xv.w * q.w;
        a[4 + h] = xv.x * k.x + xv.y * k.y + xv.z * k.z + xv.w * k.w;
    }
#pragma unroll
    for (int off = 16; off; off >>= 1) {
#pragma unroll
        for (int h = 0; h < 8; h++) a[h] += __shfl_xor_sync(0xffffffffu, a[h], off);
    }
    if (lane == 0) {
        g_hq[w] = make_float4(a[0], a[1], a[2], a[3]);
        float4 kk;
        kk.x = a[4] >= 0.f ? a[4] : NEG * a[4];
        kk.y = a[5] >= 0.f ? a[5] : NEG * a[5];
        kk.z = a[6] >= 0.f ? a[6] : NEG * a[6];
        kk.w = a[7] >= 0.f ? a[7] : NEG * a[7];
        g_kact[w] = kk;
    }
}

// ---------------- h_proj GEMM: [NN,128] = x[NN,128] @ Wl^T[128,128] + bl ---
__global__ __launch_bounds__(256) void kgemm(const float* __restrict__ x,
                                             const float* __restrict__ Wl,
                                             const float* __restrict__ bl) {
    __shared__ float xs[64 * 65];
    __shared__ float ws[64 * 65];
    int nb = blockIdx.x * 64;
    int ob = blockIdx.y * 64;
    int tid = threadIdx.x;
    int tx = tid & 15;   // outs:  o = tx + 16*oo
    int ty = tid >> 4;   // nodes: n = ty*4 + nn
    float acc[4][4];
#pragma unroll
    for (int a = 0; a < 4; a++)
#pragma unroll
        for (int b = 0; b < 4; b++) acc[a][b] = 0.f;

    for (int kb = 0; kb < 128; kb += 64) {
        for (int idx = tid; idx < 64 * 16; idx += 256) {
            int row = idx >> 4, c = idx & 15;
            float4 v = make_float4(0.f, 0.f, 0.f, 0.f);
            if (nb + row < NN) v = ((const float4*)x)[(nb + row) * 32 + (kb >> 2) + c];
            xs[row * 65 + c * 4 + 0] = v.x;
            xs[row * 65 + c * 4 + 1] = v.y;
            xs[row * 65 + c * 4 + 2] = v.z;
            xs[row * 65 + c * 4 + 3] = v.w;
            float4 wv = ((const float4*)Wl)[(ob + row) * 32 + (kb >> 2) + c];
            ws[row * 65 + c * 4 + 0] = wv.x;
            ws[row * 65 + c * 4 + 1] = wv.y;
            ws[row * 65 + c * 4 + 2] = wv.z;
            ws[row * 65 + c * 4 + 3] = wv.w;
        }
        __syncthreads();
#pragma unroll 4
        for (int k = 0; k < 64; k++) {
            float xr[4], wr[4];
#pragma unroll
            for (int nn = 0; nn < 4; nn++) xr[nn] = xs[(ty * 4 + nn) * 65 + k];
#pragma unroll
            for (int oo = 0; oo < 4; oo++) wr[oo] = ws[(tx + 16 * oo) * 65 + k];
#pragma unroll
            for (int nn = 0; nn < 4; nn++)
#pragma unroll
                for (int oo = 0; oo < 4; oo++) acc[nn][oo] = fmaf(xr[nn], wr[oo], acc[nn][oo]);
        }
        __syncthreads();
    }
#pragma unroll
    for (int nn = 0; nn < 4; nn++) {
        int n = nb + ty * 4 + nn;
        if (n >= NN) continue;
#pragma unroll
        for (int oo = 0; oo < 4; oo++) {
            int o = ob + tx + 16 * oo;
            g_hproj[n * 128 + o] = __float2half_rn(acc[nn][oo] + __ldg(&bl[o]));
        }
    }
}

// ---------------- q_agg: per-node sum of h_q over incoming edges -----------
__global__ __launch_bounds__(512) void kqagg() {
    int i = (blockIdx.x * blockDim.x + threadIdx.x) >> 5;
    int lane = threadIdx.x & 31;
    if (i >= NN) return;
    int beg = g_rowptr[i], end = g_rowptr[i + 1];
    float4 a = make_float4(0.f, 0.f, 0.f, 0.f);
    for (int j = beg + lane; j < end; j += 32) {
        float4 q = g_hq[g_ccol[j]];
        a.x += q.x; a.y += q.y; a.z += q.z; a.w += q.w;
    }
#pragma unroll
    for (int off = 16; off; off >>= 1) {
        a.x += __shfl_xor_sync(0xffffffffu, a.x, off);
        a.y += __shfl_xor_sync(0xffffffffu, a.y, off);
        a.z += __shfl_xor_sync(0xffffffffu, a.z, off);
        a.w += __shfl_xor_sync(0xffffffffu, a.w, off);
    }
    if (lane == 0) g_qagg[i] = a;
}

// ---------------- fused softmax + aggregation + leaky ----------------------
__global__ __launch_bounds__(512) void kmain(float* __restrict__ out) {
    int i = (blockIdx.x * blockDim.x + threadIdx.x) >> 5;
    int lane = threadIdx.x & 31;
    if (i >= NN) return;
    int beg = g_rowptr[i], end = g_rowptr[i + 1];
    float4 k = g_kact[i];

    // pass 1: gather q_agg, compute scores, stage them, segment max per head
    float m0 = -1e30f, m1 = -1e30f, m2 = -1e30f, m3 = -1e30f;
    for (int j = beg + lane; j < end; j += 32) {
        float4 q = g_qagg[__ldg(&g_ccol[j])];
        float4 s;
        s.x = k.x * q.x; s.y = k.y * q.y; s.z = k.z * q.z; s.w = k.w * q.w;
        g_sc[j] = s;
        m0 = fmaxf(m0, s.x); m1 = fmaxf(m1, s.y);
        m2 = fmaxf(m2, s.z); m3 = fmaxf(m3, s.w);
    }
#pragma unroll
    for (int off = 16; off; off >>= 1) {
        m0 = fmaxf(m0, __shfl_xor_sync(0xffffffffu, m0, off));
        m1 = fmaxf(m1, __shfl_xor_sync(0xffffffffu, m1, off));
        m2 = fmaxf(m2, __shfl_xor_sync(0xffffffffu, m2, off));
        m3 = fmaxf(m3, __shfl_xor_sync(0xffffffffu, m3, off));
    }

    // pass 2: exponentiate once, store back, accumulate sums
    float s0 = 0.f, s1 = 0.f, s2 = 0.f, s3 = 0.f;
    for (int j = beg + lane; j < end; j += 32) {
        float4 sc = g_sc[j];
        float4 e;
        e.x = __expf(sc.x - m0); e.y = __expf(sc.y - m1);
        e.z = __expf(sc.z - m2); e.w = __expf(sc.w - m3);
        g_sc[j] = e;
        s0 += e.x; s1 += e.y; s2 += e.z; s3 += e.w;
    }
#pragma unroll
    for (int off = 16; off; off >>= 1) {
        s0 += __shfl_xor_sync(0xffffffffu, s0, off);
        s1 += __shfl_xor_sync(0xffffffffu, s1, off);
        s2 += __shfl_xor_sync(0xffffffffu, s2, off);
        s3 += __shfl_xor_sync(0xffffffffu, s3, off);
    }
    float i0 = 0.25f / (s0 + 1e-8f);
    float i1 = 0.25f / (s1 + 1e-8f);
    float i2 = 0.25f / (s2 + 1e-8f);
    float i3 = 0.25f / (s3 + 1e-8f);

    // pass 3: weighted aggregation of fp16 h_proj[col]
    float4 acc = make_float4(0.f, 0.f, 0.f, 0.f);
    for (int base = beg; base < end; base += 32) {
        int j = base + lane;
        int c = 0;
        float w = 0.f;
        if (j < end) {
            c = __ldg(&g_ccol[j]);
            float4 e = g_sc[j];
            w = e.x * i0 + e.y * i1 + e.z * i2 + e.w * i3;
        }
        int cnt = min(32, end - base);
        for (int jj = 0; jj < cnt; jj++) {
            int cc = __shfl_sync(0xffffffffu, c, jj);
            float ww = __shfl_sync(0xffffffffu, w, jj);
            uint2 hv = ((const uint2*)g_hproj)[cc * 32 + lane];
            float2 f01 = __half22float2(*(__half2*)&hv.x);
            float2 f23 = __half22float2(*(__half2*)&hv.y);
            acc.x = fmaf(ww, f01.x, acc.x);
            acc.y = fmaf(ww, f01.y, acc.y);
            acc.z = fmaf(ww, f23.x, acc.z);
            acc.w = fmaf(ww, f23.y, acc.w);
        }
    }
    float4 o;
    o.x = acc.x >= 0.f ? acc.x : NEG * acc.x;
    o.y = acc.y >= 0.f ? acc.y : NEG * acc.y;
    o.z = acc.z >= 0.f ? acc.z : NEG * acc.z;
    o.w = acc.w >= 0.f ? acc.w : NEG * acc.w;
    ((float4*)out)[i * 32 + lane] = o;
}

// ---------------- launch ----------------
extern "C" void kernel_launch(void* const* d_in, const int* in_sizes, int n_in,
                              void* d_out, int out_size) {
    const float* x  = (const float*)d_in[0];
    const int*   ei = (const int*)d_in[1];
    const float* Wq = (const float*)d_in[2];
    const float* Wk = (const float*)d_in[3];
    const float* Wl = (const float*)d_in[4];
    const float* bl = (const float*)d_in[5];
    float* out = (float*)d_out;

    kzero<<<(NN + 255) / 256, 256>>>();
    khist<<<(NE + 255) / 256, 256>>>(ei);
    kscan<<<1, 1024>>>();
    kscatter<<<(NE + 255) / 256, 256>>>(ei);
    kprojsmall<<<(NN * 32 + 255) / 256, 256>>>(x, Wq, Wk);
    kgemm<<<dim3((NN + 63) / 64, 2), 256>>>(x, Wl, bl);
    kqagg<<<(NN * 32 + 511) / 512, 512>>>();
    kmain<<<(NN * 32 + 511) / 512, 512>>>(out);
}

// round 5
// speedup vs baseline: 1.4564x; 1.4564x over previous
#include <cuda_runtime.h>

#define NN 50000
#define NE 1600000
#define NEG 0.2f
#define W 128           // ELL width (in-degree is Poisson(32); max ~65)
#define NOVF 65536      // overflow insurance capacity

// ---------------- scratch (device globals; no allocation allowed) ----------
__device__ float4 g_hq[NN];          // per-node h_q (4 heads)
__device__ float4 g_kact[NN];        // per-node leaky(x@Wk^T)
__device__ float4 g_qagg[NN];        // per-node aggregated q
__device__ float  g_hproj[NN * 128]; // per-node x@Wl^T + bl (fp32)
__device__ int    g_deg[NN];
__device__ int    g_ell[NN * W];     // ELL adjacency: cols of incoming edges
__device__ int    g_ovf_r[NOVF];
__device__ int    g_ovf_c[NOVF];
__device__ int    g_novf;

// ---------------- init ----------------
__global__ void kzero() {
    int i = blockIdx.x * blockDim.x + threadIdx.x;
    if (i < NN) g_deg[i] = 0;
    if (i == 0) g_novf = 0;
}

// ---------------- single-pass ELL build ----------------
__global__ void kbuild(const int* __restrict__ ei) {
    int e = blockIdx.x * blockDim.x + threadIdx.x;
    if (e >= NE) return;
    int r = ei[e];
    int c = ei[NE + e];
    int p = atomicAdd(&g_deg[r], 1);
    if (p < W) {
        g_ell[r * W + p] = c;
    } else {
        int o = atomicAdd(&g_novf, 1);
        if (o < NOVF) { g_ovf_r[o] = r; g_ovf_c[o] = c; }
    }
}

// ---------------- per-node small projections: h_q, k_act -------------------
__global__ void kprojsmall(const float* __restrict__ x,
                           const float* __restrict__ Wq,
                           const float* __restrict__ Wk) {
    int w = (blockIdx.x * blockDim.x + threadIdx.x) >> 5;
    int lane = threadIdx.x & 31;
    if (w >= NN) return;
    float4 xv = ((const float4*)x)[w * 32 + lane];
    float a[8];
#pragma unroll
    for (int h = 0; h < 4; h++) {
        float4 q = ((const float4*)Wq)[h * 32 + lane];
        float4 k = ((const float4*)Wk)[h * 32 + lane];
        a[h]     = xv.x * q.x + xv.y * q.y + xv.z * q.z + xv.w * q.w;
        a[4 + h] = xv.x * k.x + xv.y * k.y + xv.z * k.z + xv.w * k.w;
    }
#pragma unroll
    for (int off = 16; off; off >>= 1) {
#pragma unroll
        for (int h = 0; h < 8; h++) a[h] += __shfl_xor_sync(0xffffffffu, a[h], off);
    }
    if (lane == 0) {
        g_hq[w] = make_float4(a[0], a[1], a[2], a[3]);
        float4 kk;
        kk.x = a[4] >= 0.f ? a[4] : NEG * a[4];
        kk.y = a[5] >= 0.f ? a[5] : NEG * a[5];
        kk.z = a[6] >= 0.f ? a[6] : NEG * a[6];
        kk.w = a[7] >= 0.f ? a[7] : NEG * a[7];
        g_kact[w] = kk;
    }
}

// ---------------- h_proj GEMM: [NN,128] = x[NN,128] @ Wl^T[128,128] + bl ---
__global__ __launch_bounds__(256) void kgemm(const float* __restrict__ x,
                                             const float* __restrict__ Wl,
                                             const float* __restrict__ bl) {
    __shared__ float xs[64 * 65];
    __shared__ float ws[64 * 65];
    int nb = blockIdx.x * 64;
    int ob = blockIdx.y * 64;
    int tid = threadIdx.x;
    int tx = tid & 15;   // outs:  o = tx + 16*oo
    int ty = tid >> 4;   // nodes: n = ty*4 + nn
    float acc[4][4];
#pragma unroll
    for (int a = 0; a < 4; a++)
#pragma unroll
        for (int b = 0; b < 4; b++) acc[a][b] = 0.f;

    for (int kb = 0; kb < 128; kb += 64) {
        for (int idx = tid; idx < 64 * 16; idx += 256) {
            int row = idx >> 4, c = idx & 15;
            float4 v = make_float4(0.f, 0.f, 0.f, 0.f);
            if (nb + row < NN) v = ((const float4*)x)[(nb + row) * 32 + (kb >> 2) + c];
            xs[row * 65 + c * 4 + 0] = v.x;
            xs[row * 65 + c * 4 + 1] = v.y;
            xs[row * 65 + c * 4 + 2] = v.z;
            xs[row * 65 + c * 4 + 3] = v.w;
            float4 wv = ((const float4*)Wl)[(ob + row) * 32 + (kb >> 2) + c];
            ws[row * 65 + c * 4 + 0] = wv.x;
            ws[row * 65 + c * 4 + 1] = wv.y;
            ws[row * 65 + c * 4 + 2] = wv.z;
            ws[row * 65 + c * 4 + 3] = wv.w;
        }
        __syncthreads();
#pragma unroll 4
        for (int k = 0; k < 64; k++) {
            float xr[4], wr[4];
#pragma unroll
            for (int nn = 0; nn < 4; nn++) xr[nn] = xs[(ty * 4 + nn) * 65 + k];
#pragma unroll
            for (int oo = 0; oo < 4; oo++) wr[oo] = ws[(tx + 16 * oo) * 65 + k];
#pragma unroll
            for (int nn = 0; nn < 4; nn++)
#pragma unroll
                for (int oo = 0; oo < 4; oo++) acc[nn][oo] = fmaf(xr[nn], wr[oo], acc[nn][oo]);
        }
        __syncthreads();
    }
#pragma unroll
    for (int nn = 0; nn < 4; nn++) {
        int n = nb + ty * 4 + nn;
        if (n >= NN) continue;
#pragma unroll
        for (int oo = 0; oo < 4; oo++) {
            int o = ob + tx + 16 * oo;
            g_hproj[n * 128 + o] = acc[nn][oo] + __ldg(&bl[o]);
        }
    }
}

// ---------------- q_agg: per-node sum of h_q over incoming edges -----------
__global__ __launch_bounds__(512) void kqagg() {
    int i = (blockIdx.x * blockDim.x + threadIdx.x) >> 5;
    int lane = threadIdx.x & 31;
    if (i >= NN) return;
    int deg = g_deg[i];
    int degE = min(deg, W);
    float4 a = make_float4(0.f, 0.f, 0.f, 0.f);
    for (int k = lane; k < degE; k += 32) {
        float4 q = g_hq[g_ell[i * W + k]];
        a.x += q.x; a.y += q.y; a.z += q.z; a.w += q.w;
    }
    if (deg > W) {  // insurance path (never taken for this input)
        int n = min(g_novf, NOVF);
        for (int t = lane; t < n; t += 32) {
            if (g_ovf_r[t] == i) {
                float4 q = g_hq[g_ovf_c[t]];
                a.x += q.x; a.y += q.y; a.z += q.z; a.w += q.w;
            }
        }
    }
#pragma unroll
    for (int off = 16; off; off >>= 1) {
        a.x += __shfl_xor_sync(0xffffffffu, a.x, off);
        a.y += __shfl_xor_sync(0xffffffffu, a.y, off);
        a.z += __shfl_xor_sync(0xffffffffu, a.z, off);
        a.w += __shfl_xor_sync(0xffffffffu, a.w, off);
    }
    if (lane == 0) g_qagg[i] = a;
}

// ---------------- fused softmax + aggregation + leaky ----------------------
__global__ __launch_bounds__(512) void kmain(float* __restrict__ out) {
    int i = (blockIdx.x * blockDim.x + threadIdx.x) >> 5;
    int lane = threadIdx.x & 31;
    if (i >= NN) return;
    int deg = g_deg[i];
    int degE = min(deg, W);
    float4 kc = g_kact[i];

    // pass 1: gather q_agg, scores into registers, segment max per head
    float4 sc[4];
    int col[4];
    float m0 = -1e30f, m1 = -1e30f, m2 = -1e30f, m3 = -1e30f;
#pragma unroll
    for (int ch = 0; ch < 4; ch++) {
        int k = ch * 32 + lane;
        sc[ch] = make_float4(-1e30f, -1e30f, -1e30f, -1e30f);
        col[ch] = 0;
        if (ch * 32 < degE && k < degE) {
            int c = __ldg(&g_ell[i * W + k]);
            col[ch] = c;
            float4 q = g_qagg[c];
            sc[ch].x = kc.x * q.x; sc[ch].y = kc.y * q.y;
            sc[ch].z = kc.z * q.z; sc[ch].w = kc.w * q.w;
        }
        m0 = fmaxf(m0, sc[ch].x); m1 = fmaxf(m1, sc[ch].y);
        m2 = fmaxf(m2, sc[ch].z); m3 = fmaxf(m3, sc[ch].w);
    }
    if (deg > W) {  // insurance
        int n = min(g_novf, NOVF);
        for (int t = lane; t < n; t += 32) {
            if (g_ovf_r[t] == i) {
                float4 q = g_qagg[g_ovf_c[t]];
                m0 = fmaxf(m0, kc.x * q.x); m1 = fmaxf(m1, kc.y * q.y);
                m2 = fmaxf(m2, kc.z * q.z); m3 = fmaxf(m3, kc.w * q.w);
            }
        }
    }
#pragma unroll
    for (int off = 16; off; off >>= 1) {
        m0 = fmaxf(m0, __shfl_xor_sync(0xffffffffu, m0, off));
        m1 = fmaxf(m1, __shfl_xor_sync(0xffffffffu, m1, off));
        m2 = fmaxf(m2, __shfl_xor_sync(0xffffffffu, m2, off));
        m3 = fmaxf(m3, __shfl_xor_sync(0xffffffffu, m3, off));
    }

    // pass 2: exp in registers, accumulate sums
    float s0 = 0.f, s1 = 0.f, s2 = 0.f, s3 = 0.f;
#pragma unroll
    for (int ch = 0; ch < 4; ch++) {
        // invalid lanes hold -1e30 -> exp underflows to 0 when deg>0
        sc[ch].x = __expf(sc[ch].x - m0); sc[ch].y = __expf(sc[ch].y - m1);
        sc[ch].z = __expf(sc[ch].z - m2); sc[ch].w = __expf(sc[ch].w - m3);
        int k = ch * 32 + lane;
        if (k >= degE) sc[ch] = make_float4(0.f, 0.f, 0.f, 0.f);
        s0 += sc[ch].x; s1 += sc[ch].y; s2 += sc[ch].z; s3 += sc[ch].w;
    }
    if (deg > W) {  // insurance
        int n = min(g_novf, NOVF);
        for (int t = lane; t < n; t += 32) {
            if (g_ovf_r[t] == i) {
                float4 q = g_qagg[g_ovf_c[t]];
                s0 += __expf(kc.x * q.x - m0); s1 += __expf(kc.y * q.y - m1);
                s2 += __expf(kc.z * q.z - m2); s3 += __expf(kc.w * q.w - m3);
            }
        }
    }
#pragma unroll
    for (int off = 16; off; off >>= 1) {
        s0 += __shfl_xor_sync(0xffffffffu, s0, off);
        s1 += __shfl_xor_sync(0xffffffffu, s1, off);
        s2 += __shfl_xor_sync(0xffffffffu, s2, off);
        s3 += __shfl_xor_sync(0xffffffffu, s3, off);
    }
    float i0 = 0.25f / (s0 + 1e-8f);
    float i1 = 0.25f / (s1 + 1e-8f);
    float i2 = 0.25f / (s2 + 1e-8f);
    float i3 = 0.25f / (s3 + 1e-8f);

    // pass 3: weighted aggregation of h_proj[col]
    float4 acc = make_float4(0.f, 0.f, 0.f, 0.f);
#pragma unroll
    for (int ch = 0; ch < 4; ch++) {
        int base = ch * 32;
        if (base >= degE) break;
        float w = sc[ch].x * i0 + sc[ch].y * i1 + sc[ch].z * i2 + sc[ch].w * i3;
        int cnt = min(32, degE - base);
#pragma unroll 4
        for (int jj = 0; jj < cnt; jj++) {
            int cc = __shfl_sync(0xffffffffu, col[ch], jj);
            float ww = __shfl_sync(0xffffffffu, w, jj);
            float4 hp = ((const float4*)g_hproj)[cc * 32 + lane];
            acc.x = fmaf(ww, hp.x, acc.x);
            acc.y = fmaf(ww, hp.y, acc.y);
            acc.z = fmaf(ww, hp.z, acc.z);
            acc.w = fmaf(ww, hp.w, acc.w);
        }
    }
    if (deg > W) {  // insurance: scalar broadcast over overflow list
        int n = min(g_novf, NOVF);
        for (int t = 0; t < n; t++) {
            int rr = g_ovf_r[t];
            if (rr == i) {
                int cc = g_ovf_c[t];
                float4 q = g_qagg[cc];
                float ww = __expf(kc.x * q.x - m0) * i0 + __expf(kc.y * q.y - m1) * i1 +
                           __expf(kc.z * q.z - m2) * i2 + __expf(kc.w * q.w - m3) * i3;
                float4 hp = ((const float4*)g_hproj)[cc * 32 + lane];
                acc.x = fmaf(ww, hp.x, acc.x);
                acc.y = fmaf(ww, hp.y, acc.y);
                acc.z = fmaf(ww, hp.z, acc.z);
                acc.w = fmaf(ww, hp.w, acc.w);
            }
        }
    }
    float4 o;
    o.x = acc.x >= 0.f ? acc.x : NEG * acc.x;
    o.y = acc.y >= 0.f ? acc.y : NEG * acc.y;
    o.z = acc.z >= 0.f ? acc.z : NEG * acc.z;
    o.w = acc.w >= 0.f ? acc.w : NEG * acc.w;
    ((float4*)out)[i * 32 + lane] = o;
}

// ---------------- launch ----------------
extern "C" void kernel_launch(void* const* d_in, const int* in_sizes, int n_in,
                              void* d_out, int out_size) {
    const float* x  = (const float*)d_in[0];
    const int*   ei = (const int*)d_in[1];
    const float* Wq = (const float*)d_in[2];
    const float* Wk = (const float*)d_in[3];
    const float* Wl = (const float*)d_in[4];
    const float* bl = (const float*)d_in[5];
    float* out = (float*)d_out;

    kzero<<<(NN + 255) / 256, 256>>>();
    kbuild<<<(NE + 255) / 256, 256>>>(ei);
    kprojsmall<<<(NN * 32 + 255) / 256, 256>>>(x, Wq, Wk);
    kgemm<<<dim3((NN + 63) / 64, 2), 256>>>(x, Wl, bl);
    kqagg<<<(NN * 32 + 511) / 512, 512>>>();
    kmain<<<(NN * 32 + 511) / 512, 512>>>(out);
}

// round 6
// speedup vs baseline: 1.4842x; 1.0191x over previous
#include <cuda_runtime.h>

#define NN 50000
#define NE 1600000
#define NEG 0.2f
#define W 128           // ELL width (in-degree is Poisson(32); max ~65)
#define NOVF 65536      // overflow insurance capacity

// ---------------- scratch (device globals; no allocation allowed) ----------
__device__ float4 g_hq[NN];          // per-node h_q (4 heads)
__device__ float4 g_kact[NN];        // per-node leaky(x@Wk^T)
__device__ float4 g_qagg[NN];        // per-node aggregated q
__device__ float  g_hproj[NN * 128]; // per-node x@Wl^T + bl (fp32)
__device__ int    g_deg[NN];
__device__ int    g_ell[NN * W];     // ELL adjacency: cols of incoming edges
__device__ int    g_ovf_r[NOVF];
__device__ int    g_ovf_c[NOVF];
__device__ int    g_novf;

// ---------------- init ----------------
__global__ void kzero() {
    int i = blockIdx.x * blockDim.x + threadIdx.x;
    if (i < NN) g_deg[i] = 0;
    if (i == 0) g_novf = 0;
}

// ---------------- single-pass ELL build, 4 edges/thread for MLP ------------
__global__ void kbuild(const int* __restrict__ ei) {
    int t = blockIdx.x * blockDim.x + threadIdx.x;
    int e0 = t * 4;
    if (e0 >= NE) return;
    int4 r4 = *(const int4*)&ei[e0];
    int4 c4 = *(const int4*)&ei[NE + e0];
    int rr[4] = {r4.x, r4.y, r4.z, r4.w};
    int cc[4] = {c4.x, c4.y, c4.z, c4.w};
    int pp[4];
#pragma unroll
    for (int j = 0; j < 4; j++) pp[j] = atomicAdd(&g_deg[rr[j]], 1);
#pragma unroll
    for (int j = 0; j < 4; j++) {
        if (pp[j] < W) {
            g_ell[rr[j] * W + pp[j]] = cc[j];
        } else {
            int o = atomicAdd(&g_novf, 1);
            if (o < NOVF) { g_ovf_r[o] = rr[j]; g_ovf_c[o] = cc[j]; }
        }
    }
}

// ---------------- per-node small projections: h_q, k_act -------------------
__global__ void kprojsmall(const float* __restrict__ x,
                           const float* __restrict__ Wq,
                           const float* __restrict__ Wk) {
    int w = (blockIdx.x * blockDim.x + threadIdx.x) >> 5;
    int lane = threadIdx.x & 31;
    if (w >= NN) return;
    float4 xv = ((const float4*)x)[w * 32 + lane];
    float a[8];
#pragma unroll
    for (int h = 0; h < 4; h++) {
        float4 q = ((const float4*)Wq)[h * 32 + lane];
        float4 k = ((const float4*)Wk)[h * 32 + lane];
        a[h]     = xv.x * q.x + xv.y * q.y + xv.z * q.z + xv.w * q.w;
        a[4 + h] = xv.x * k.x + xv.y * k.y + xv.z * k.z + xv.w * k.w;
    }
#pragma unroll
    for (int off = 16; off; off >>= 1) {
#pragma unroll
        for (int h = 0; h < 8; h++) a[h] += __shfl_xor_sync(0xffffffffu, a[h], off);
    }
    if (lane == 0) {
        g_hq[w] = make_float4(a[0], a[1], a[2], a[3]);
        float4 kk;
        kk.x = a[4] >= 0.f ? a[4] : NEG * a[4];
        kk.y = a[5] >= 0.f ? a[5] : NEG * a[5];
        kk.z = a[6] >= 0.f ? a[6] : NEG * a[6];
        kk.w = a[7] >= 0.f ? a[7] : NEG * a[7];
        g_kact[w] = kk;
    }
}

// ---------------- h_proj GEMM: [NN,128] = x[NN,128] @ Wl^T[128,128] + bl ---
// 128x128 tile per block, 256 threads, 8x8 register tile, k-major smem,
// vectorized LDS.128 (stride 132 floats keeps 16B alignment for all k).
__global__ __launch_bounds__(256) void kgemm(const float* __restrict__ x,
                                             const float* __restrict__ Wl,
                                             const float* __restrict__ bl) {
    __shared__ float xs[32 * 132];
    __shared__ float ws[32 * 132];
    int nb = blockIdx.x * 128;
    int tid = threadIdx.x;
    int tx = tid & 15;   // outs:  o = tx*8 + oo
    int ty = tid >> 4;   // nodes: n = nb + ty*8 + nn
    float acc[8][8];
#pragma unroll
    for (int a = 0; a < 8; a++)
#pragma unroll
        for (int b = 0; b < 8; b++) acc[a][b] = 0.f;

    for (int kb = 0; kb < 32; kb += 8) {  // kb counts float4s (8 f4 = 32 floats)
#pragma unroll
        for (int it = 0; it < 4; it++) {
            int idx = tid + it * 256;      // 0..1023
            int row = idx >> 3, c = idx & 7;
            float4 v = make_float4(0.f, 0.f, 0.f, 0.f);
            if (nb + row < NN) v = ((const float4*)x)[(nb + row) * 32 + kb + c];
            xs[(4 * c + 0) * 132 + row] = v.x;
            xs[(4 * c + 1) * 132 + row] = v.y;
            xs[(4 * c + 2) * 132 + row] = v.z;
            xs[(4 * c + 3) * 132 + row] = v.w;
            float4 wv = ((const float4*)Wl)[row * 32 + kb + c];
            ws[(4 * c + 0) * 132 + row] = wv.x;
            ws[(4 * c + 1) * 132 + row] = wv.y;
            ws[(4 * c + 2) * 132 + row] = wv.z;
            ws[(4 * c + 3) * 132 + row] = wv.w;
        }
        __syncthreads();
#pragma unroll 8
        for (int k = 0; k < 32; k++) {
            float4 xa = *(const float4*)&xs[k * 132 + ty * 8];
            float4 xb = *(const float4*)&xs[k * 132 + ty * 8 + 4];
            float4 wa = *(const float4*)&ws[k * 132 + tx * 8];
            float4 wb = *(const float4*)&ws[k * 132 + tx * 8 + 4];
            float xr[8] = {xa.x, xa.y, xa.z, xa.w, xb.x, xb.y, xb.z, xb.w};
            float wr[8] = {wa.x, wa.y, wa.z, wa.w, wb.x, wb.y, wb.z, wb.w};
#pragma unroll
            for (int nn = 0; nn < 8; nn++)
#pragma unroll
                for (int oo = 0; oo < 8; oo++)
                    acc[nn][oo] = fmaf(xr[nn], wr[oo], acc[nn][oo]);
        }
        __syncthreads();
    }
    float b[8];
#pragma unroll
    for (int oo = 0; oo < 8; oo++) b[oo] = __ldg(&bl[tx * 8 + oo]);
#pragma unroll
    for (int nn = 0; nn < 8; nn++) {
        int n = nb + ty * 8 + nn;
        if (n >= NN) continue;
        float4 o0 = make_float4(acc[nn][0] + b[0], acc[nn][1] + b[1],
                                acc[nn][2] + b[2], acc[nn][3] + b[3]);
        float4 o1 = make_float4(acc[nn][4] + b[4], acc[nn][5] + b[5],
                                acc[nn][6] + b[6], acc[nn][7] + b[7]);
        ((float4*)g_hproj)[n * 32 + tx * 2 + 0] = o0;
        ((float4*)g_hproj)[n * 32 + tx * 2 + 1] = o1;
    }
}

// ---------------- q_agg: per-node sum of h_q over incoming edges -----------
__global__ __launch_bounds__(512) void kqagg() {
    int i = (blockIdx.x * blockDim.x + threadIdx.x) >> 5;
    int lane = threadIdx.x & 31;
    if (i >= NN) return;
    int deg = g_deg[i];
    int degE = min(deg, W);
    float4 a = make_float4(0.f, 0.f, 0.f, 0.f);
    for (int k = lane; k < degE; k += 32) {
        float4 q = g_hq[g_ell[i * W + k]];
        a.x += q.x; a.y += q.y; a.z += q.z; a.w += q.w;
    }
    if (deg > W) {  // insurance path (never taken for this input)
        int n = min(g_novf, NOVF);
        for (int t = lane; t < n; t += 32) {
            if (g_ovf_r[t] == i) {
                float4 q = g_hq[g_ovf_c[t]];
                a.x += q.x; a.y += q.y; a.z += q.z; a.w += q.w;
            }
        }
    }
#pragma unroll
    for (int off = 16; off; off >>= 1) {
        a.x += __shfl_xor_sync(0xffffffffu, a.x, off);
        a.y += __shfl_xor_sync(0xffffffffu, a.y, off);
        a.z += __shfl_xor_sync(0xffffffffu, a.z, off);
        a.w += __shfl_xor_sync(0xffffffffu, a.w, off);
    }
    if (lane == 0) g_qagg[i] = a;
}

// ---------------- fused softmax + aggregation + leaky ----------------------
__global__ __launch_bounds__(512) void kmain(float* __restrict__ out) {
    int i = (blockIdx.x * blockDim.x + threadIdx.x) >> 5;
    int lane = threadIdx.x & 31;
    if (i >= NN) return;
    int deg = g_deg[i];
    int degE = min(deg, W);
    float4 kc = g_kact[i];

    // pass 1: gather q_agg, scores into registers, segment max per head
    float4 sc[4];
    int col[4];
    float m0 = -1e30f, m1 = -1e30f, m2 = -1e30f, m3 = -1e30f;
#pragma unroll
    for (int ch = 0; ch < 4; ch++) {
        int k = ch * 32 + lane;
        sc[ch] = make_float4(-1e30f, -1e30f, -1e30f, -1e30f);
        col[ch] = 0;
        if (ch * 32 < degE && k < degE) {
            int c = __ldg(&g_ell[i * W + k]);
            col[ch] = c;
            float4 q = g_qagg[c];
            sc[ch].x = kc.x * q.x; sc[ch].y = kc.y * q.y;
            sc[ch].z = kc.z * q.z; sc[ch].w = kc.w * q.w;
        }
        m0 = fmaxf(m0, sc[ch].x); m1 = fmaxf(m1, sc[ch].y);
        m2 = fmaxf(m2, sc[ch].z); m3 = fmaxf(m3, sc[ch].w);
    }
    if (deg > W) {  // insurance
        int n = min(g_novf, NOVF);
        for (int t = lane; t < n; t += 32) {
            if (g_ovf_r[t] == i) {
                float4 q = g_qagg[g_ovf_c[t]];
                m0 = fmaxf(m0, kc.x * q.x); m1 = fmaxf(m1, kc.y * q.y);
                m2 = fmaxf(m2, kc.z * q.z); m3 = fmaxf(m3, kc.w * q.w);
            }
        }
    }
#pragma unroll
    for (int off = 16; off; off >>= 1) {
        m0 = fmaxf(m0, __shfl_xor_sync(0xffffffffu, m0, off));
        m1 = fmaxf(m1, __shfl_xor_sync(0xffffffffu, m1, off));
        m2 = fmaxf(m2, __shfl_xor_sync(0xffffffffu, m2, off));
        m3 = fmaxf(m3, __shfl_xor_sync(0xffffffffu, m3, off));
    }

    // pass 2: exp in registers, accumulate sums
    float s0 = 0.f, s1 = 0.f, s2 = 0.f, s3 = 0.f;
#pragma unroll
    for (int ch = 0; ch < 4; ch++) {
        sc[ch].x = __expf(sc[ch].x - m0); sc[ch].y = __expf(sc[ch].y - m1);
        sc[ch].z = __expf(sc[ch].z - m2); sc[ch].w = __expf(sc[ch].w - m3);
        int k = ch * 32 + lane;
        if (k >= degE) sc[ch] = make_float4(0.f, 0.f, 0.f, 0.f);
        s0 += sc[ch].x; s1 += sc[ch].y; s2 += sc[ch].z; s3 += sc[ch].w;
    }
    if (deg > W) {  // insurance
        int n = min(g_novf, NOVF);
        for (int t = lane; t < n; t += 32) {
            if (g_ovf_r[t] == i) {
                float4 q = g_qagg[g_ovf_c[t]];
                s0 += __expf(kc.x * q.x - m0); s1 += __expf(kc.y * q.y - m1);
                s2 += __expf(kc.z * q.z - m2); s3 += __expf(kc.w * q.w - m3);
            }
        }
    }
#pragma unroll
    for (int off = 16; off; off >>= 1) {
        s0 += __shfl_xor_sync(0xffffffffu, s0, off);
        s1 += __shfl_xor_sync(0xffffffffu, s1, off);
        s2 += __shfl_xor_sync(0xffffffffu, s2, off);
        s3 += __shfl_xor_sync(0xffffffffu, s3, off);
    }
    float i0 = 0.25f / (s0 + 1e-8f);
    float i1 = 0.25f / (s1 + 1e-8f);
    float i2 = 0.25f / (s2 + 1e-8f);
    float i3 = 0.25f / (s3 + 1e-8f);

    // pass 3: weighted aggregation of h_proj[col]
    float4 acc = make_float4(0.f, 0.f, 0.f, 0.f);
#pragma unroll
    for (int ch = 0; ch < 4; ch++) {
        int base = ch * 32;
        if (base >= degE) break;
        float w = sc[ch].x * i0 + sc[ch].y * i1 + sc[ch].z * i2 + sc[ch].w * i3;
        int cnt = min(32, degE - base);
#pragma unroll 4
        for (int jj = 0; jj < cnt; jj++) {
            int cc = __shfl_sync(0xffffffffu, col[ch], jj);
            float ww = __shfl_sync(0xffffffffu, w, jj);
            float4 hp = ((const float4*)g_hproj)[cc * 32 + lane];
            acc.x = fmaf(ww, hp.x, acc.x);
            acc.y = fmaf(ww, hp.y, acc.y);
            acc.z = fmaf(ww, hp.z, acc.z);
            acc.w = fmaf(ww, hp.w, acc.w);
        }
    }
    if (deg > W) {  // insurance: scalar broadcast over overflow list
        int n = min(g_novf, NOVF);
        for (int t = 0; t < n; t++) {
            int rr = g_ovf_r[t];
            if (rr == i) {
                int cc = g_ovf_c[t];
                float4 q = g_qagg[cc];
                float ww = __expf(kc.x * q.x - m0) * i0 + __expf(kc.y * q.y - m1) * i1 +
                           __expf(kc.z * q.z - m2) * i2 + __expf(kc.w * q.w - m3) * i3;
                float4 hp = ((const float4*)g_hproj)[cc * 32 + lane];
                acc.x = fmaf(ww, hp.x, acc.x);
                acc.y = fmaf(ww, hp.y, acc.y);
                acc.z = fmaf(ww, hp.z, acc.z);
                acc.w = fmaf(ww, hp.w, acc.w);
            }
        }
    }
    float4 o;
    o.x = acc.x >= 0.f ? acc.x : NEG * acc.x;
    o.y = acc.y >= 0.f ? acc.y : NEG * acc.y;
    o.z = acc.z >= 0.f ? acc.z : NEG * acc.z;
    o.w = acc.w >= 0.f ? acc.w : NEG * acc.w;
    ((float4*)out)[i * 32 + lane] = o;
}

// ---------------- launch ----------------
extern "C" void kernel_launch(void* const* d_in, const int* in_sizes, int n_in,
                              void* d_out, int out_size) {
    const float* x  = (const float*)d_in[0];
    const int*   ei = (const int*)d_in[1];
    const float* Wq = (const float*)d_in[2];
    const float* Wk = (const float*)d_in[3];
    const float* Wl = (const float*)d_in[4];
    const float* bl = (const float*)d_in[5];
    float* out = (float*)d_out;

    kzero<<<(NN + 255) / 256, 256>>>();
    kbuild<<<(NE / 4 + 255) / 256, 256>>>(ei);
    kprojsmall<<<(NN * 32 + 255) / 256, 256>>>(x, Wq, Wk);
    kgemm<<<(NN + 127) / 128, 256>>>(x, Wl, bl);
    kqagg<<<(NN * 32 + 511) / 512, 512>>>();
    kmain<<<(NN * 32 + 511) / 512, 512>>>(out);
}